// round 8
// baseline (speedup 1.0000x reference)
#include <cuda_runtime.h>
#include <cuda_bf16.h>

// VariableGroupNorm: N=32, C=256, H=W=56, G=32, ragged groups (4/12 channels).
//
// Two-kernel uniform split (replaces fused one-CTA-per-group, which plateaued
// at DRAM 61.7% due to per-CTA pass1->barrier->pass2 serialization + ragged
// 3:1 CTA imbalance):
//   K1 stats: one 128-thr CTA per (n,c) channel -> 8192 identical CTAs, each
//     reduces one contiguous 12.25 KB channel (exactly 6 float4/thread + small
//     remainder, fully unrolled). Writes per-channel (sum,sumsq) to __device__
//     scratch. No atomics -> deterministic. Pure read stream, perfect balance.
//   K2 apply: same shape. Thread 0 folds its group's <=12 channel partials
//     into scale/shift (no third kernel), then CTA streams the channel:
//     __ldcs (x lines are L2-resident across the launch boundary; only L1 is
//     flushed per launch) + fma + __stcs (write-only out, evict-first).
// DRAM traffic = 205.5 MB minimum; uniform streaming should push DRAM% from
// 62% toward 75-85%.

#define NGROUPS 32
#define NCHAN   256
#define HW      3136
#define HW4     784            // HW / 4
#define EPSV    1e-5f
#define TPB     128
#define REM     (HW4 - 6 * TPB)   // 16 threads carry a 7th element
#define MAXN    64

// Per-channel partial sums: [n * NCHAN + c] -> (sum, sumsq)
__device__ float2 g_ch[MAXN * NCHAN];

// ---------------- Kernel 1: per-channel stats ----------------
__global__ __launch_bounds__(TPB)
void vgn_stats_kernel(const float* __restrict__ x)
{
    __shared__ float s_red[8];

    const int bid = blockIdx.x;                   // (n, c) flat
    const int t   = threadIdx.x;
    const float4* __restrict__ xb =
        reinterpret_cast<const float4*>(x + (size_t)bid * HW);

    // 6 unconditional vec loads (t + k*128 <= 127+640 = 767 < 784), 1 predicated.
    const float4 v0 = __ldg(&xb[t]);
    const float4 v1 = __ldg(&xb[t + TPB]);
    const float4 v2 = __ldg(&xb[t + 2 * TPB]);
    const float4 v3 = __ldg(&xb[t + 3 * TPB]);
    const float4 v4 = __ldg(&xb[t + 4 * TPB]);
    const float4 v5 = __ldg(&xb[t + 5 * TPB]);
    float4 v6 = make_float4(0.f, 0.f, 0.f, 0.f);
    if (t < REM) v6 = __ldg(&xb[t + 6 * TPB]);

    float s  = ((v0.x + v0.y) + (v0.z + v0.w)) + ((v1.x + v1.y) + (v1.z + v1.w))
             + ((v2.x + v2.y) + (v2.z + v2.w)) + ((v3.x + v3.y) + (v3.z + v3.w))
             + ((v4.x + v4.y) + (v4.z + v4.w)) + ((v5.x + v5.y) + (v5.z + v5.w))
             + ((v6.x + v6.y) + (v6.z + v6.w));
    float sq = (v0.x * v0.x + v0.y * v0.y) + (v0.z * v0.z + v0.w * v0.w)
             + (v1.x * v1.x + v1.y * v1.y) + (v1.z * v1.z + v1.w * v1.w)
             + (v2.x * v2.x + v2.y * v2.y) + (v2.z * v2.z + v2.w * v2.w)
             + (v3.x * v3.x + v3.y * v3.y) + (v3.z * v3.z + v3.w * v3.w)
             + (v4.x * v4.x + v4.y * v4.y) + (v4.z * v4.z + v4.w * v4.w)
             + (v5.x * v5.x + v5.y * v5.y) + (v5.z * v5.z + v5.w * v5.w)
             + (v6.x * v6.x + v6.y * v6.y) + (v6.z * v6.z + v6.w * v6.w);

    #pragma unroll
    for (int o = 16; o > 0; o >>= 1) {
        s  += __shfl_xor_sync(0xffffffffu, s,  o);
        sq += __shfl_xor_sync(0xffffffffu, sq, o);
    }
    const int wid = t >> 5;
    if ((t & 31) == 0) { s_red[wid] = s; s_red[4 + wid] = sq; }
    __syncthreads();
    if (t == 0) {
        float ts = (s_red[0] + s_red[1]) + (s_red[2] + s_red[3]);
        float tq = (s_red[4] + s_red[5]) + (s_red[6] + s_red[7]);
        g_ch[bid] = make_float2(ts, tq);
    }
}

// ---------------- Kernel 2: per-channel apply ----------------
__global__ __launch_bounds__(TPB)
void vgn_apply_kernel(const float* __restrict__ x,
                      const float* __restrict__ gamma,
                      const float* __restrict__ beta,
                      const int*   __restrict__ gs_raw,
                      float* __restrict__ out)
{
    __shared__ float s_scale;
    __shared__ float s_shift;

    const int bid = blockIdx.x;
    const int n   = bid >> 8;      // bid / NCHAN
    const int c   = bid & 255;     // bid % NCHAN
    const int t   = threadIdx.x;

    if (t == 0) {
        // Dtype hedge: group_sizes may land as int32 or int64 (low words).
        int sum1 = 0;
        #pragma unroll
        for (int i = 0; i < NGROUPS; ++i) sum1 += gs_raw[i];
        const int stride = (sum1 == NCHAN) ? 1 : 2;

        // Locate the group containing channel c.
        int g = 0, c0 = 0, cs = gs_raw[0];
        #pragma unroll
        for (int i = 0; i < NGROUPS; ++i) {
            const int sz = gs_raw[i * stride];
            if (c >= c0 && c < c0 + sz) { g = i; cs = sz; break; }
            c0 += sz;
        }

        // Fold the group's channel partials (deterministic serial order).
        float ts = 0.f, tq = 0.f;
        for (int ch = c0; ch < c0 + cs; ++ch) {
            const float2 v = g_ch[n * NCHAN + ch];
            ts += v.x; tq += v.y;
        }
        const float cnt  = (float)cs * (float)HW;
        const float mean = ts / cnt;
        const float var  = tq / cnt - mean * mean;
        const float sc   = gamma[g] * rsqrtf(var + EPSV);
        s_scale = sc;
        s_shift = beta[g] - mean * sc;
    }
    __syncthreads();

    const float sc = s_scale;
    const float sh = s_shift;

    const size_t base = (size_t)bid * HW;
    const float4* __restrict__ xb = reinterpret_cast<const float4*>(x + base);
    float4* __restrict__       ob = reinterpret_cast<float4*>(out + base);

    // 6 unconditional vecs + 1 predicated; loads batched, stores after.
    float4 v0 = __ldcs(&xb[t]);
    float4 v1 = __ldcs(&xb[t + TPB]);
    float4 v2 = __ldcs(&xb[t + 2 * TPB]);
    float4 v3 = __ldcs(&xb[t + 3 * TPB]);
    float4 v4 = __ldcs(&xb[t + 4 * TPB]);
    float4 v5 = __ldcs(&xb[t + 5 * TPB]);
    float4 v6;
    if (t < REM) v6 = __ldcs(&xb[t + 6 * TPB]);

    v0.x = fmaf(v0.x, sc, sh); v0.y = fmaf(v0.y, sc, sh);
    v0.z = fmaf(v0.z, sc, sh); v0.w = fmaf(v0.w, sc, sh);
    v1.x = fmaf(v1.x, sc, sh); v1.y = fmaf(v1.y, sc, sh);
    v1.z = fmaf(v1.z, sc, sh); v1.w = fmaf(v1.w, sc, sh);
    v2.x = fmaf(v2.x, sc, sh); v2.y = fmaf(v2.y, sc, sh);
    v2.z = fmaf(v2.z, sc, sh); v2.w = fmaf(v2.w, sc, sh);
    v3.x = fmaf(v3.x, sc, sh); v3.y = fmaf(v3.y, sc, sh);
    v3.z = fmaf(v3.z, sc, sh); v3.w = fmaf(v3.w, sc, sh);
    v4.x = fmaf(v4.x, sc, sh); v4.y = fmaf(v4.y, sc, sh);
    v4.z = fmaf(v4.z, sc, sh); v4.w = fmaf(v4.w, sc, sh);
    v5.x = fmaf(v5.x, sc, sh); v5.y = fmaf(v5.y, sc, sh);
    v5.z = fmaf(v5.z, sc, sh); v5.w = fmaf(v5.w, sc, sh);

    __stcs(&ob[t], v0);
    __stcs(&ob[t + TPB], v1);
    __stcs(&ob[t + 2 * TPB], v2);
    __stcs(&ob[t + 3 * TPB], v3);
    __stcs(&ob[t + 4 * TPB], v4);
    __stcs(&ob[t + 5 * TPB], v5);
    if (t < REM) {
        v6.x = fmaf(v6.x, sc, sh); v6.y = fmaf(v6.y, sc, sh);
        v6.z = fmaf(v6.z, sc, sh); v6.w = fmaf(v6.w, sc, sh);
        __stcs(&ob[t + 6 * TPB], v6);
    }
}

extern "C" void kernel_launch(void* const* d_in, const int* in_sizes, int n_in,
                              void* d_out, int out_size)
{
    const float* x     = (const float*)d_in[0];
    const float* gamma = (const float*)d_in[1];
    const float* beta  = (const float*)d_in[2];
    const int*   gs    = (const int*)d_in[3];
    float*       out   = (float*)d_out;

    const int nbatch = in_sizes[0] / (NCHAN * HW);  // 32
    const int nchan_blocks = nbatch * NCHAN;        // 8192

    vgn_stats_kernel<<<nchan_blocks, TPB>>>(x);
    vgn_apply_kernel<<<nchan_blocks, TPB>>>(x, gamma, beta, gs, out);
}